// round 14
// baseline (speedup 1.0000x reference)
#include <cuda_runtime.h>
#include <math.h>

// Problem constants
#define D_     512
#define TD_    1024
#define NSYM_  512
#define NCON_  64
#define NV_    256
#define NPOS_  16384
#define DEPTH_ 6
#define EPS_   1e-8f
#define CC_    0.25f
#define SCALE_ 0.04419417382415922f   // 512^-0.5

#define NBLOCKS 592    // 4 blocks/SM x 148 SMs
#define NTHR    128

typedef unsigned long long ull;
typedef unsigned int uint32;

// ---------------------------------------------------------------------------
// fp32 tables
// ---------------------------------------------------------------------------
__device__ float g_z0[NV_*TD_];
__device__ float g_cellTab[NSYM_*TD_];
__device__ float g_C2[NSYM_*TD_];
__device__ float g_C3[NSYM_*TD_];
__device__ float g_lookOut[NSYM_*NV_];
__device__ float g_Ksym[NSYM_*D_];
__device__ float g_Vsym[NSYM_*TD_];
__device__ float g_Qtab[NSYM_*D_];
__device__ float g_QK[NSYM_*NSYM_];
__device__ float g_CS[NSYM_*NSYM_];
__device__ float g_VS[NSYM_*NSYM_];
__device__ float g_Z0S[NV_*NSYM_];
__device__ float g_sym2[NSYM_];
__device__ float g_conDist[NSYM_];
__device__ int   g_hist[NV_];
__device__ int   g_fin[NV_];
__device__ float g_symLv[NV_];
__device__ float g_conLv[NV_];
__device__ ull   g_barCnt;

// ---------------------------------------------------------------------------
// Pre-split tf32 hi/lo operand tables (columns stored pos-reordered per 16)
// ---------------------------------------------------------------------------
__device__ uint32 sH_sym[NSYM_*TD_],  sL_sym[NSYM_*TD_];
__device__ uint32 sH_emb[NV_*TD_],    sL_emb[NV_*TD_];
__device__ uint32 sH_W2[TD_*TD_],     sL_W2[TD_*TD_];
__device__ uint32 sH_kw[D_*TD_],      sL_kw[D_*TD_];
__device__ uint32 sH_vw[TD_*TD_],     sL_vw[TD_*TD_];
__device__ uint32 sH_qw[D_*TD_],      sL_qw[D_*TD_];
__device__ uint32 sH_dw[NV_*TD_],     sL_dw[NV_*TD_];
__device__ uint32 sH_cell[NSYM_*TD_], sL_cell[NSYM_*TD_];
__device__ uint32 sH_C2[NSYM_*TD_],   sL_C2[NSYM_*TD_];
__device__ uint32 sH_C3[NSYM_*TD_],   sL_C3[NSYM_*TD_];
__device__ uint32 sH_Vs[NSYM_*TD_],   sL_Vs[NSYM_*TD_];
__device__ uint32 sH_z0[NV_*TD_],     sL_z0[NV_*TD_];
__device__ uint32 sH_Qt[NSYM_*D_],    sL_Qt[NSYM_*D_];
__device__ uint32 sH_Ks[NSYM_*D_],    sL_Ks[NSYM_*D_];

// ---------------------------------------------------------------------------
// Grid-wide barrier
// ---------------------------------------------------------------------------
__device__ __forceinline__ void grid_barrier()
{
    __syncthreads();
    if (threadIdx.x == 0) {
        __threadfence();
        ull t = atomicAdd(&g_barCnt, 1ULL) + 1ULL;
        ull target = ((t - 1ULL) / NBLOCKS + 1ULL) * NBLOCKS;
        while (*(volatile ull*)&g_barCnt < target) { }
        __threadfence();
    }
    __syncthreads();
}

// ---------------------------------------------------------------------------
// tf32 helpers
// ---------------------------------------------------------------------------
__device__ __forceinline__ void mma_tf32(float* d, const uint32* a, const uint32* b)
{
    asm volatile("mma.sync.aligned.m16n8k8.row.col.f32.tf32.tf32.f32 "
        "{%0,%1,%2,%3}, {%4,%5,%6,%7}, {%8,%9}, {%0,%1,%2,%3};"
        : "+f"(d[0]), "+f"(d[1]), "+f"(d[2]), "+f"(d[3])
        : "r"(a[0]), "r"(a[1]), "r"(a[2]), "r"(a[3]), "r"(b[0]), "r"(b[1]));
}

// column reorder within each 16-col tile: pos = (k>>3)*8 + (k&3)*2 + ((k>>2)&1)
__device__ __forceinline__ int poscol(int c)
{
    return (c & ~15) | ((((c >> 3) & 1) << 3) | (((c & 3) << 1) + ((c >> 2) & 1)));
}

// split one fp32 value to hi/lo tf32 and store at pos-reordered column c
__device__ __forceinline__ void split_write(uint32* H, uint32* L, size_t rowBase,
                                            int c, float f)
{
    uint32 h; asm("cvt.rna.tf32.f32 %0, %1;" : "=r"(h) : "f"(f));
    float r = f - __uint_as_float(h);
    uint32 l; asm("cvt.rna.tf32.f32 %0, %1;" : "=r"(l) : "f"(r));
    int p = poscol(c);
    H[rowBase + p] = h; L[rowBase + p] = l;
}

// split 4 rows of an fp32 matrix [rows][K] into H/L
__device__ void dev_split_rows(const float* __restrict__ src, uint32* H, uint32* L,
                               int row0, int K)
{
#pragma unroll
    for (int rr = 0; rr < 4; rr++) {
        int r = row0 + rr;
        size_t base = (size_t)r * K;
        for (int c = threadIdx.x * 4; c < K; c += NTHR * 4) {
            float4 v = *(const float4*)(src + base + c);
            split_write(H, L, base, c + 0, v.x);
            split_write(H, L, base, c + 1, v.y);
            split_write(H, L, base, c + 2, v.z);
            split_write(H, L, base, c + 3, v.w);
        }
    }
}

// ---------------------------------------------------------------------------
// Tensor-core GEMM tile 64x64, 128 threads, 3xTF32 from PRE-SPLIT operands.
// Double-buffered smem, pure-copy loader. CELL=1: cell epilogue to [M,1024].
// ---------------------------------------------------------------------------
#define RS     20
#define PLANE  (64*RS)       // 1280 words
#define PLANEB (4*PLANE)     // 5120 words per buffer
#define TGSM   (2*PLANEB)    // 10240 words = 40 KB

template<int CELL>
__device__ void dev_gemm_tc(const uint32* __restrict__ AH, const uint32* __restrict__ AL,
                            const uint32* __restrict__ BH, const uint32* __restrict__ BL,
                            const float* __restrict__ bias,
                            float* __restrict__ C, uint32* CH, uint32* CL,
                            int N, int K, int bx, int by, float* smf)
{
    uint32* smu = (uint32*)smf;
    const int tid = threadIdx.x;
    const int warp = tid >> 5, lane = tid & 31;
    const int g = lane >> 2, tg = lane & 3;
    const int wm = (warp & 1) * 32, wn = (warp >> 1) * 32;
    const int m0 = by * 64, n0 = bx * 64;

    const int r0 = tid >> 2, q4 = (tid & 3) << 2;
    const int r1 = r0 + 32;
    const size_t aO0 = (size_t)(m0 + r0) * K + q4;
    const size_t aO1 = (size_t)(m0 + r1) * K + q4;
    const size_t bO0 = (size_t)(n0 + r0) * K + q4;
    const size_t bO1 = (size_t)(n0 + r1) * K + q4;

    float d[2][4][4];
#pragma unroll
    for (int i = 0; i < 2; i++)
#pragma unroll
        for (int j = 0; j < 4; j++)
#pragma unroll
            for (int c = 0; c < 4; c++) d[i][j][c] = 0.f;

    const int nk = K >> 4;    // always even here (K = 512 or 1024)

    uint4 vah0 = *(const uint4*)(AH + aO0);
    uint4 vah1 = *(const uint4*)(AH + aO1);
    uint4 val0 = *(const uint4*)(AL + aO0);
    uint4 val1 = *(const uint4*)(AL + aO1);
    uint4 vbh0 = *(const uint4*)(BH + bO0);
    uint4 vbh1 = *(const uint4*)(BH + bO1);
    uint4 vbl0 = *(const uint4*)(BL + bO0);
    uint4 vbl1 = *(const uint4*)(BL + bO1);

    // store tile 0 into buffer 0
    {
        uint32* p = smu;
        *(uint4*)(p + r0*RS + q4)           = vah0;
        *(uint4*)(p + r1*RS + q4)           = vah1;
        *(uint4*)(p + PLANE + r0*RS + q4)   = val0;
        *(uint4*)(p + PLANE + r1*RS + q4)   = val1;
        *(uint4*)(p + 2*PLANE + r0*RS + q4) = vbh0;
        *(uint4*)(p + 2*PLANE + r1*RS + q4) = vbh1;
        *(uint4*)(p + 3*PLANE + r0*RS + q4) = vbl0;
        *(uint4*)(p + 3*PLANE + r1*RS + q4) = vbl1;
    }
    __syncthreads();

    for (int t = 0; t < nk; t++) {
        if (t + 1 < nk) {
            size_t o = (size_t)(t + 1) * 16;
            vah0 = *(const uint4*)(AH + aO0 + o);
            vah1 = *(const uint4*)(AH + aO1 + o);
            val0 = *(const uint4*)(AL + aO0 + o);
            val1 = *(const uint4*)(AL + aO1 + o);
            vbh0 = *(const uint4*)(BH + bO0 + o);
            vbh1 = *(const uint4*)(BH + bO1 + o);
            vbl0 = *(const uint4*)(BL + bO0 + o);
            vbl1 = *(const uint4*)(BL + bO1 + o);
        }

        {   // compute from buffer t&1
            uint32* Ah = smu + (t & 1) * PLANEB;
            uint32* Al = Ah + PLANE;
            uint32* Bh = Al + PLANE;
            uint32* Bl = Bh + PLANE;
#pragma unroll
            for (int kf = 0; kf < 2; kf++) {
                const int pbase = kf*8 + tg*2;
                uint32 ah[2][4], al[2][4];
#pragma unroll
                for (int mf = 0; mf < 2; mf++) {
                    int ra = (wm + mf*16 + g)*RS + pbase;
                    int rb = ra + 8*RS;
                    uint2 h0 = *(const uint2*)(Ah + ra);
                    uint2 h1 = *(const uint2*)(Ah + rb);
                    uint2 l0 = *(const uint2*)(Al + ra);
                    uint2 l1 = *(const uint2*)(Al + rb);
                    ah[mf][0] = h0.x; ah[mf][1] = h1.x; ah[mf][2] = h0.y; ah[mf][3] = h1.y;
                    al[mf][0] = l0.x; al[mf][1] = l1.x; al[mf][2] = l0.y; al[mf][3] = l1.y;
                }
                uint32 bh[4][2], bl[4][2];
#pragma unroll
                for (int nf = 0; nf < 4; nf++) {
                    int rb = (wn + nf*8 + g)*RS + pbase;
                    uint2 h = *(const uint2*)(Bh + rb);
                    uint2 l = *(const uint2*)(Bl + rb);
                    bh[nf][0] = h.x; bh[nf][1] = h.y;
                    bl[nf][0] = l.x; bl[nf][1] = l.y;
                }
#pragma unroll
                for (int mf = 0; mf < 2; mf++)
#pragma unroll
                    for (int nf = 0; nf < 4; nf++) {
                        mma_tf32(d[mf][nf], ah[mf], bh[nf]);
                        mma_tf32(d[mf][nf], al[mf], bh[nf]);
                        mma_tf32(d[mf][nf], ah[mf], bl[nf]);
                    }
            }
        }

        if (t + 1 < nk) {
            uint32* p = smu + ((t + 1) & 1) * PLANEB;
            *(uint4*)(p + r0*RS + q4)           = vah0;
            *(uint4*)(p + r1*RS + q4)           = vah1;
            *(uint4*)(p + PLANE + r0*RS + q4)   = val0;
            *(uint4*)(p + PLANE + r1*RS + q4)   = val1;
            *(uint4*)(p + 2*PLANE + r0*RS + q4) = vbh0;
            *(uint4*)(p + 2*PLANE + r1*RS + q4) = vbh1;
            *(uint4*)(p + 3*PLANE + r0*RS + q4) = vbl0;
            *(uint4*)(p + 3*PLANE + r1*RS + q4) = vbl1;
            __syncthreads();
        }
    }

    if (!CELL) {
#pragma unroll
        for (int mf = 0; mf < 2; mf++)
#pragma unroll
            for (int nf = 0; nf < 4; nf++) {
                int r = m0 + wm + mf*16 + g;
                int c = n0 + wn + nf*8 + 2*tg;
                float b0v = bias ? bias[c]   : 0.f;
                float b1v = bias ? bias[c+1] : 0.f;
                float v00 = d[mf][nf][0] + b0v, v01 = d[mf][nf][1] + b1v;
                float v10 = d[mf][nf][2] + b0v, v11 = d[mf][nf][3] + b1v;
                C[(size_t)r*N + c]         = v00;
                C[(size_t)r*N + c + 1]     = v01;
                C[(size_t)(r+8)*N + c]     = v10;
                C[(size_t)(r+8)*N + c + 1] = v11;
                if (CH) {
                    split_write(CH, CL, (size_t)r*N,     c,   v00);
                    split_write(CH, CL, (size_t)r*N,     c+1, v01);
                    split_write(CH, CL, (size_t)(r+8)*N, c,   v10);
                    split_write(CH, CL, (size_t)(r+8)*N, c+1, v11);
                }
            }
    } else {
#pragma unroll
        for (int mf = 0; mf < 2; mf++)
#pragma unroll
            for (int nf = 0; nf < 4; nf++) {
                int r = m0 + wm + mf*16 + g;
                int p = ((n0 + wn + nf*8) >> 1) + tg;
#pragma unroll
                for (int h = 0; h < 2; h++) {
                    int rr = r + h*8;
                    float lr = d[mf][nf][0 + 2*h], li = d[mf][nf][1 + 2*h];
                    float mm = sqrtf(lr*lr + li*li + EPS_);
                    float zr = tanhf(lr / (1.f + mm));
                    float zi = tanhf(li / (1.f + mm));
                    C[(size_t)rr*TD_ + p]      = zr;
                    C[(size_t)rr*TD_ + p + D_] = zi;
                    if (CH) {
                        split_write(CH, CL, (size_t)rr*TD_, p,      zr);
                        split_write(CH, CL, (size_t)rr*TD_, p + D_, zi);
                    }
                }
            }
    }
}

// ---------------------------------------------------------------------------
// Prep units (1249): embed+split | W2 build+split | sym2 | conDist | hist |
//                    split sym/kw/vw/qw/dec_w
// ---------------------------------------------------------------------------
__device__ void dev_prep(int b, const float* __restrict__ mag,
                         const float* __restrict__ phase,
                         const float* __restrict__ Wr, const float* __restrict__ Wi,
                         const float* __restrict__ sym, const float* __restrict__ con,
                         const float* __restrict__ kw, const float* __restrict__ vw,
                         const float* __restrict__ qw, const float* __restrict__ dec_w,
                         const int* __restrict__ x, float* sm)
{
    const int tid = threadIdx.x;

    if (b < 32) {                          // embed (split only)
        int base = b * 8;
#pragma unroll
        for (int vv = 0; vv < 8; vv++) {
            int v = base + vv;
            size_t rb = (size_t)v * TD_;
            for (int i = tid; i < D_; i += NTHR) {
                float r = mag[v*D_ + i];
                float t = phase[v*D_ + i];
                split_write(sH_emb, sL_emb, rb, i,      r * cosf(t));
                split_write(sH_emb, sL_emb, rb, i + D_, r * sinf(t));
            }
        }
    } else if (b < 288) {                  // W2int build + split: 4 rows per unit
        int idx = b - 32;
#pragma unroll
        for (int rr = 0; rr < 4; rr++) {
            int r = idx*4 + rr;
            int n = r >> 1;
            int odd = r & 1;
            size_t rb = (size_t)r * TD_;
            for (int k = tid*4; k < TD_; k += NTHR*4) {
                float4 v;
                if (k < D_) {
                    v = *(const float4*)((odd ? Wi : Wr) + (size_t)n*D_ + k);
                } else {
                    int k2 = k - D_;
                    if (odd) v = *(const float4*)(Wr + (size_t)n*D_ + k2);
                    else {
                        v = *(const float4*)(Wi + (size_t)n*D_ + k2);
                        v.x = -v.x; v.y = -v.y; v.z = -v.z; v.w = -v.w;
                    }
                }
                split_write(sH_W2, sL_W2, rb, k+0, v.x);
                split_write(sH_W2, sL_W2, rb, k+1, v.y);
                split_write(sH_W2, sL_W2, rb, k+2, v.z);
                split_write(sH_W2, sL_W2, rb, k+3, v.w);
            }
        }
    } else if (b < 416) {                  // sym2: 4 rows per unit
        int local = b - 288;
        int w = tid >> 5, lane = tid & 31;
        int row = local*4 + w;
        float s = 0.f;
        const float* src = sym + (size_t)row*TD_;
        for (int i = lane; i < TD_; i += 32) { float v = src[i]; s += v*v; }
#pragma unroll
        for (int o = 16; o > 0; o >>= 1) s += __shfl_down_sync(0xffffffffu, s, o);
        if (lane == 0) g_sym2[row] = s;
    } else if (b < 544) {                  // conDist: 4 rows per unit
        int local = b - 416;
        int w = tid >> 5, lane = tid & 31;
        int row = local*4 + w;
        float sv[32];
#pragma unroll
        for (int c = 0; c < 32; c++) sv[c] = sym[(size_t)row*TD_ + c*32 + lane];
        float best = 1e30f;
        for (int j = 0; j < NCON_; j++) {
            const float* cj = con + (size_t)j*TD_;
            float s = 0.f;
#pragma unroll
            for (int c = 0; c < 32; c++) { float d = sv[c] - cj[c*32 + lane]; s += d*d; }
#pragma unroll
            for (int o = 16; o > 0; o >>= 1) s += __shfl_xor_sync(0xffffffffu, s, o);
            best = fminf(best, s);
        }
        if (lane == 0) g_conDist[row] = best;
    } else if (b == 544) {                 // histogram of x
        int* hist = (int*)sm;
        hist[tid] = 0; hist[tid + 128] = 0; __syncthreads();
        for (int i = tid; i < NPOS_; i += NTHR) atomicAdd(&hist[x[i]], 1);
        __syncthreads();
        g_hist[tid] = hist[tid];
        g_hist[tid + 128] = hist[tid + 128];
        __syncthreads();
    } else if (b < 673) {                  // split sym
        dev_split_rows(sym, sH_sym, sL_sym, (b - 545)*4, TD_);
    } else if (b < 801) {                  // split kw
        dev_split_rows(kw, sH_kw, sL_kw, (b - 673)*4, TD_);
    } else if (b < 1057) {                 // split vw
        dev_split_rows(vw, sH_vw, sL_vw, (b - 801)*4, TD_);
    } else if (b < 1185) {                 // split qw
        dev_split_rows(qw, sH_qw, sL_qw, (b - 1057)*4, TD_);
    } else {                               // split dec_w (b < 1249)
        dev_split_rows(dec_w, sH_dw, sL_dw, (b - 1185)*4, TD_);
    }
}

// ---------------------------------------------------------------------------
// Trajectory (one unit = one vocab id, 128 threads)
// ---------------------------------------------------------------------------
__device__ void dev_trajectory(int v, float* sm)
{
    float* red   = sm;
    float* sdist = sm + 128;
    int*   sidx  = (int*)(sm + 256);
    int*   memIdx= (int*)(sm + 384);
    float* wsh   = sm + 392;
    float* shconf= sm + 400;
    const int tid = threadIdx.x;

    float part = 0.f;
    for (int i = tid; i < TD_; i += NTHR) { float z = g_z0[(size_t)v*TD_ + i]; part += z*z; }
    red[tid] = part; __syncthreads();
    for (int st = 64; st > 0; st >>= 1) { if (tid < st) red[tid] += red[tid+st]; __syncthreads(); }
    float z2 = red[0];
    __syncthreads();

    float bd = 1e30f; int bi = 0;
    for (int kp = tid; kp < NSYM_; kp += NTHR) {
        float d = z2 + g_sym2[kp] - 2.f*g_Z0S[(size_t)v*NSYM_ + kp];
        if (d < bd) { bd = d; bi = kp; }
    }
    sdist[tid] = bd; sidx[tid] = bi; __syncthreads();
    for (int st = 64; st > 0; st >>= 1) {
        if (tid < st) {
            float d2 = sdist[tid+st]; int i2 = sidx[tid+st];
            if (d2 < sdist[tid] || (d2 == sdist[tid] && i2 < sidx[tid])) { sdist[tid] = d2; sidx[tid] = i2; }
        }
        __syncthreads();
    }
    int si = sidx[0]; float sd = sdist[0];
    if (tid == 0) { memIdx[0] = si; shconf[0] = 1.f/(1.f + sd); }
    float symL = sd;
    float conL = g_conDist[si];
    __syncthreads();

    for (int d = 1; d < DEPTH_; d++) {
        int k = memIdx[d-1];
        if (tid == 0) {
            float sc[DEPTH_]; float mx = -1e30f;
            float cf = shconf[0];
            for (int j = 0; j < d; j++) {
                float s = g_QK[(size_t)k*NSYM_ + memIdx[j]] * SCALE_ * cf;
                sc[j] = s; if (s > mx) mx = s;
            }
            float se = 0.f;
            for (int j = 0; j < d; j++) { sc[j] = expf(sc[j]-mx); se += sc[j]; }
            for (int j = 0; j < d; j++) wsh[j] = sc[j]/se;
        }
        __syncthreads();

        part = 0.f;
        for (int i = tid; i < TD_; i += NTHR) {
            float z = g_cellTab[(size_t)k*TD_ + i];
            for (int j = 0; j < d; j++)
                z += 0.1f * wsh[j] * g_Vsym[(size_t)memIdx[j]*TD_ + i];
            part += z*z;
        }
        red[tid] = part; __syncthreads();
        for (int st = 64; st > 0; st >>= 1) { if (tid < st) red[tid] += red[tid+st]; __syncthreads(); }
        z2 = red[0];
        __syncthreads();

        bd = 1e30f; bi = 0;
        for (int kp = tid; kp < NSYM_; kp += NTHR) {
            float zdot = g_CS[(size_t)k*NSYM_ + kp];
            for (int j = 0; j < d; j++)
                zdot += 0.1f * wsh[j] * g_VS[(size_t)memIdx[j]*NSYM_ + kp];
            float dist = z2 + g_sym2[kp] - 2.f*zdot;
            if (dist < bd) { bd = dist; bi = kp; }
        }
        sdist[tid] = bd; sidx[tid] = bi; __syncthreads();
        for (int st = 64; st > 0; st >>= 1) {
            if (tid < st) {
                float d2 = sdist[tid+st]; int i2 = sidx[tid+st];
                if (d2 < sdist[tid] || (d2 == sdist[tid] && i2 < sidx[tid])) { sdist[tid] = d2; sidx[tid] = i2; }
            }
            __syncthreads();
        }
        si = sidx[0]; sd = sdist[0];
        if (tid == 0) { memIdx[d] = si; shconf[0] = 1.f/(1.f + sd); }
        symL += sd;
        conL += g_conDist[si];
        __syncthreads();
    }

    if (tid == 0) {
        g_fin[v]   = memIdx[DEPTH_-1];
        g_symLv[v] = symL;
        g_conLv[v] = conL;
    }
    __syncthreads();
}

// ---------------------------------------------------------------------------
// Persistent mega-kernel
// ---------------------------------------------------------------------------
__global__ __launch_bounds__(NTHR, 4)
void mega_kernel(const int* __restrict__ x,
                 const float* __restrict__ mag, const float* __restrict__ phase,
                 const float* __restrict__ Wr,  const float* __restrict__ Wi,
                 const float* __restrict__ qw,  const float* __restrict__ qb,
                 const float* __restrict__ kw,  const float* __restrict__ kb,
                 const float* __restrict__ vw,  const float* __restrict__ vb,
                 const float* __restrict__ dec_w, const float* __restrict__ dec_b,
                 const float* __restrict__ sym, const float* __restrict__ con,
                 float* __restrict__ out, int writeLoss)
{
    __shared__ float sm[TGSM];
    const int b0 = blockIdx.x;

    // ---- L0: prep (1249 units) ----
    for (int u = b0; u < 1249; u += NBLOCKS)
        dev_prep(u, mag, phase, Wr, Wi, sym, con, kw, vw, qw, dec_w, x, sm);
    grid_barrier();

    // ---- L1 (384): cellTab(128) | z0(64) | Ksym(64) | Vsym(128) ----
    for (int u = b0; u < 384; u += NBLOCKS) {
        if (u < 128) {
            dev_gemm_tc<1>(sH_sym, sL_sym, sH_W2, sL_W2, nullptr,
                           g_cellTab, sH_cell, sL_cell, TD_, TD_, u & 15, u >> 4, sm);
        } else if (u < 192) {
            int t = u - 128;
            dev_gemm_tc<1>(sH_emb, sL_emb, sH_W2, sL_W2, nullptr,
                           g_z0, sH_z0, sL_z0, TD_, TD_, t & 15, t >> 4, sm);
        } else if (u < 256) {
            int t = u - 192;
            dev_gemm_tc<0>(sH_sym, sL_sym, sH_kw, sL_kw, kb,
                           g_Ksym, sH_Ks, sL_Ks, D_, TD_, t & 7, t >> 3, sm);
        } else {
            int t = u - 256;
            dev_gemm_tc<0>(sH_sym, sL_sym, sH_vw, sL_vw, vb,
                           g_Vsym, sH_Vs, sL_Vs, TD_, TD_, t & 15, t >> 4, sm);
        }
    }
    grid_barrier();

    // ---- L2 (352): C2(128) | Qtab(64) | CS(64) | VS(64) | Z0S(32) ----
    for (int u = b0; u < 352; u += NBLOCKS) {
        if (u < 128) {
            dev_gemm_tc<1>(sH_cell, sL_cell, sH_W2, sL_W2, nullptr,
                           g_C2, sH_C2, sL_C2, TD_, TD_, u & 15, u >> 4, sm);
        } else if (u < 192) {
            int t = u - 128;
            dev_gemm_tc<0>(sH_cell, sL_cell, sH_qw, sL_qw, qb,
                           g_Qtab, sH_Qt, sL_Qt, D_, TD_, t & 7, t >> 3, sm);
        } else if (u < 256) {
            int t = u - 192;
            dev_gemm_tc<0>(sH_cell, sL_cell, sH_sym, sL_sym, nullptr,
                           g_CS, nullptr, nullptr, NSYM_, TD_, t & 7, t >> 3, sm);
        } else if (u < 320) {
            int t = u - 256;
            dev_gemm_tc<0>(sH_Vs, sL_Vs, sH_sym, sL_sym, nullptr,
                           g_VS, nullptr, nullptr, NSYM_, TD_, t & 7, t >> 3, sm);
        } else {
            int t = u - 320;
            dev_gemm_tc<0>(sH_z0, sL_z0, sH_sym, sL_sym, nullptr,
                           g_Z0S, nullptr, nullptr, NSYM_, TD_, t & 7, t >> 3, sm);
        }
    }
    grid_barrier();

    // ---- L3 (192): C3(128) | QK(64) ----
    for (int u = b0; u < 192; u += NBLOCKS) {
        if (u < 128) {
            dev_gemm_tc<1>(sH_C2, sL_C2, sH_W2, sL_W2, nullptr,
                           g_C3, sH_C3, sL_C3, TD_, TD_, u & 15, u >> 4, sm);
        } else {
            int t = u - 128;
            dev_gemm_tc<0>(sH_Qt, sL_Qt, sH_Ks, sL_Ks, nullptr,
                           g_QK, nullptr, nullptr, NSYM_, D_, t & 7, t >> 3, sm);
        }
    }
    grid_barrier();

    // ---- L4 (288): lookOut(32) | trajectory(256) ----
    for (int u = b0; u < 288; u += NBLOCKS) {
        if (u < 32) {
            dev_gemm_tc<0>(sH_C3, sL_C3, sH_dw, sL_dw, dec_b,
                           g_lookOut, nullptr, nullptr, NV_, TD_, u & 3, u >> 2, sm);
        } else {
            dev_trajectory(u - 32, sm);
        }
    }
    grid_barrier();

    // ---- L5 (8193): scatter(8192) | losses(1) ----
    for (int u = b0; u < 8193; u += NBLOCKS) {
        const int tid = threadIdx.x;
        if (u < 8192) {
            int gid = u * NTHR + tid;
            int p = gid >> 6;
            int c = gid & 63;
            int v = __ldg(&x[p]);
            int f = g_fin[v];
            ((float4*)out)[gid] = ((const float4*)(g_lookOut + (size_t)f*NV_))[c];
        } else {
            float* red = sm;
            float h0 = (float)g_hist[tid], h1 = (float)g_hist[tid + 128];
            float s = h0 * g_symLv[tid] + h1 * g_symLv[tid + 128];
            float c = h0 * g_conLv[tid] + h1 * g_conLv[tid + 128];

            red[tid] = s; __syncthreads();
            for (int st = 64; st > 0; st >>= 1) { if (tid < st) red[tid] += red[tid+st]; __syncthreads(); }
            float st_tot = red[0]; __syncthreads();

            red[tid] = c; __syncthreads();
            for (int st = 64; st > 0; st >>= 1) { if (tid < st) red[tid] += red[tid+st]; __syncthreads(); }
            float ct_tot = red[0];

            if (tid == 0 && writeLoss) {
                float norm = (1.f + CC_) / (float)((size_t)NPOS_ * TD_);
                out[(size_t)NPOS_*NV_]     = st_tot * norm;
                out[(size_t)NPOS_*NV_ + 1] = ct_tot * norm;
            }
            __syncthreads();
        }
    }
}

// ---------------------------------------------------------------------------
// Host launcher
// ---------------------------------------------------------------------------
extern "C" void kernel_launch(void* const* d_in, const int* in_sizes, int n_in,
                              void* d_out, int out_size)
{
    const int*   x     = (const int*)d_in[0];
    const float* mag   = (const float*)d_in[1];
    const float* phase = (const float*)d_in[2];
    const float* Wr    = (const float*)d_in[3];
    const float* Wi    = (const float*)d_in[4];
    const float* qw    = (const float*)d_in[5];
    const float* qb    = (const float*)d_in[6];
    const float* kw    = (const float*)d_in[7];
    const float* kb    = (const float*)d_in[8];
    const float* vw    = (const float*)d_in[9];
    const float* vb    = (const float*)d_in[10];
    const float* dec_w = (const float*)d_in[11];
    const float* dec_b = (const float*)d_in[12];
    const float* sym   = (const float*)d_in[13];
    const float* con   = (const float*)d_in[14];
    float* out = (float*)d_out;

    int writeLoss = (out_size >= NPOS_*NV_ + 2) ? 1 : 0;

    mega_kernel<<<NBLOCKS, NTHR>>>(x, mag, phase, Wr, Wi, qw, qb, kw, kb,
                                   vw, vb, dec_w, dec_b, sym, con, out, writeLoss);
}